// round 10
// baseline (speedup 1.0000x reference)
#include <cuda_runtime.h>
#include <cuda_bf16.h>
#include <cstdint>

// Problem constants
#define NTOK    65536
#define DDIM    256
#define KCODES  1024
#define MLVL    4
#define TM      128            // tokens per block
#define THREADS 512
#define RS      260            // fp32 residual row stride (floats)
#define NBLOCKS (NTOK / TM)    // 512
#define MARGIN  6e-3f
// int8 quantization scales
#define SA_Q    20.0f
#define SB_Q    24576.0f
#define M2D     (-2.0f / (SA_Q * SB_Q))

// SMEM byte offsets (dynamic smem, total 218664 <= 232448; no overlays)
#define OFF_RSH    0            // 133120: [128][260] fp32 residual
#define OFF_AFRAG  133120       // 32768:  A s8 fragments [mt8][kb8][lane32] uint4
#define OFF_BBUF   165888       // 24576:  3 x 8KB B slices (ring)
#define OFF_HTD    190464       // float4 topDist[4][128] (8192) (.w = satT)
#define OFF_HTI    198656       // int4   topIdx [4][128] (8192)
#define OFF_REDD   208896       // double redD[512]       (4096)
#define OFF_E2     212992       // 4096
#define OFF_R2     217088       // 512
#define OFF_BEST   217600       // 512
#define OFF_CTOK   218112       // 512
#define OFF_CCNT   218624       // 16
#define OFF_MBAR   218640       // 3 x 8B mbarriers
#define SMEM_TOTAL 218664

__device__ float  g_e2[MLVL * KCODES];
__device__ double g_commitPartial[NBLOCKS];
// B s8 fragments: [lvl][kbslice(64)][nt16 x lane32] uint2 (4KB per kb-slice)
__device__ uint2  g_cbfrag8[MLVL * 64 * 512];

static __device__ __forceinline__ uint32_t pk8(float x0, float x1, float x2,
                                               float x3, float s) {
    int i0 = __float2int_rn(x0 * s), i1 = __float2int_rn(x1 * s);
    int i2 = __float2int_rn(x2 * s), i3 = __float2int_rn(x3 * s);
    i0 = max(-127, min(127, i0));  i1 = max(-127, min(127, i1));
    i2 = max(-127, min(127, i2));  i3 = max(-127, min(127, i3));
    return (uint32_t)(i0 & 0xff) | ((uint32_t)(i1 & 0xff) << 8)
         | ((uint32_t)(i2 & 0xff) << 16) | ((uint32_t)(i3 & 0xff) << 24);
}
static __device__ __forceinline__ void imma16832(int* c, const uint4& A,
                                                 uint32_t b0, uint32_t b1) {
    asm volatile(
        "mma.sync.aligned.m16n8k32.row.col.s32.s8.s8.s32 "
        "{%0,%1,%2,%3}, {%4,%5,%6,%7}, {%8,%9}, {%0,%1,%2,%3};"
        : "+r"(c[0]), "+r"(c[1]), "+r"(c[2]), "+r"(c[3])
        : "r"(A.x), "r"(A.y), "r"(A.z), "r"(A.w), "r"(b0), "r"(b1));
}
// ---- TMA bulk copy + mbarrier (baseline sm_90 PTX) -------------------------
static __device__ __forceinline__ void mbar_init(uint32_t a, uint32_t cnt) {
    asm volatile("mbarrier.init.shared.b64 [%0], %1;" :: "r"(a), "r"(cnt) : "memory");
}
static __device__ __forceinline__ void bulk_g2s(uint32_t dst, const void* src,
                                                uint32_t bytes, uint32_t mbar) {
    asm volatile(
        "mbarrier.arrive.expect_tx.shared.b64 _, [%2], %3;\n\t"
        "cp.async.bulk.shared::cluster.global.mbarrier::complete_tx::bytes "
        "[%0], [%1], %3, [%2];"
        :: "r"(dst), "l"(src), "r"(mbar), "r"(bytes) : "memory");
}
static __device__ __forceinline__ void mbar_wait(uint32_t a, uint32_t par) {
    asm volatile(
        "{\n\t.reg .pred p;\n\t"
        "WL_%=:\n\t"
        "mbarrier.try_wait.parity.shared::cta.b64 p, [%0], %1;\n\t"
        "@!p bra WL_%=;\n\t}"
        :: "r"(a), "r"(par) : "memory");
}
#define FENCE_PROXY_ASYNC() asm volatile("fence.proxy.async.shared::cta;" ::: "memory")

// ---------------------------------------------------------------------------
__global__ void e2_kernel(const float* __restrict__ cb) {
    int warp = (blockIdx.x * blockDim.x + threadIdx.x) >> 5;
    int lane = threadIdx.x & 31;
    if (warp >= MLVL * KCODES) return;
    const float* row = cb + (size_t)warp * DDIM;
    double s = 0.0;
#pragma unroll
    for (int m = 0; m < DDIM / 32; m++) {
        float v = row[lane + 32 * m];
        s += (double)v * (double)v;
    }
#pragma unroll
    for (int off = 16; off; off >>= 1) s += __shfl_xor_sync(0xffffffffu, s, off);
    if (lane == 0) g_e2[warp] = (float)s;
}

// ---------------------------------------------------------------------------
// Pre-pack codebooks as s8 m16n8k32 B-fragments (x SB_Q).
// [lvl][kbslice s=(nc*8+kb)][nt][lane] uint2
// b0 = c[n][k0..k0+3], b1 = c[n][k0+16..k0+19]; n = nc*128+nt*8+g, k0 = kb*32+tg*4
// ---------------------------------------------------------------------------
__global__ void prep_cb8(const float* __restrict__ cb) {
    int id = blockIdx.x * blockDim.x + threadIdx.x;
    if (id >= MLVL * 64 * 16 * 32) return;
    int lane = id & 31;
    int nt   = (id >> 5) & 15;
    int s    = (id >> 9) & 63;
    int lvl  = id >> 15;
    int nc = s >> 3, kb = s & 7;
    int g = lane >> 2, tg = lane & 3;
    int n  = nc * 128 + nt * 8 + g;
    int k0 = kb * 32 + tg * 4;
    const float* row = cb + ((size_t)lvl * KCODES + n) * DDIM;
    uint2 v;
    v.x = pk8(row[k0],      row[k0 + 1],  row[k0 + 2],  row[k0 + 3],  SB_Q);
    v.y = pk8(row[k0 + 16], row[k0 + 17], row[k0 + 18], row[k0 + 19], SB_Q);
    g_cbfrag8[id] = v;
}

// ---------------------------------------------------------------------------
struct Top4 { float d0, d1, d2, d3; int i0, i1, i2, i3; };
static __device__ __forceinline__ void t4s_insert(Top4& T, float d, int idx) {
    if (d < T.d3) {
        if (d < T.d1) {
            T.d3 = T.d2; T.i3 = T.i2;
            T.d2 = T.d1; T.i2 = T.i1;
            if (d < T.d0) { T.d1 = T.d0; T.i1 = T.i0; T.d0 = d; T.i0 = idx; }
            else          { T.d1 = d;    T.i1 = idx; }
        } else {
            if (d < T.d2) { T.d3 = T.d2; T.i3 = T.i2; T.d2 = d; T.i2 = idx; }
            else          { T.d3 = d;    T.i3 = idx; }
        }
    }
}
static __device__ __forceinline__ void t4_insert(float* d, int* i, float nd, int ni) {
    bool l3 = (nd < d[3]) || (nd == d[3] && ni < i[3]);
    if (!l3) return;
    bool l2 = (nd < d[2]) || (nd == d[2] && ni < i[2]);
    bool l1 = (nd < d[1]) || (nd == d[1] && ni < i[1]);
    bool l0 = (nd < d[0]) || (nd == d[0] && ni < i[0]);
    if (l0)      { d[3]=d[2]; i[3]=i[2]; d[2]=d[1]; i[2]=i[1]; d[1]=d[0]; i[1]=i[0]; d[0]=nd; i[0]=ni; }
    else if (l1) { d[3]=d[2]; i[3]=i[2]; d[2]=d[1]; i[2]=i[1]; d[1]=nd; i[1]=ni; }
    else if (l2) { d[3]=d[2]; i[3]=i[2]; d[2]=nd; i[2]=ni; }
    else         { d[3]=nd; i[3]=ni; }
}

// ---------------------------------------------------------------------------
// Main fused residual-VQ kernel. int8 IMMA screen + provably-complete rescue.
// 512 threads, 16 warps; warp tile 32 tokens (wm) x 32 codes (wn).
// 3-stage TMA-bulk ring of 8KB slices, 32 slices/level.
// ---------------------------------------------------------------------------
__global__ __launch_bounds__(THREADS, 1)
void rvq_mma(const float* __restrict__ X, const float* __restrict__ CB,
             float* __restrict__ Y) {
    extern __shared__ char smem[];
    float*  Rsh     = (float*)(smem + OFF_RSH);
    uint4*  Af      = (uint4*)(smem + OFF_AFRAG);
    uint2*  Bb8     = (uint2*)(smem + OFF_BBUF);
    float4* htd     = (float4*)(smem + OFF_HTD);
    int4*   hti     = (int4*)(smem + OFF_HTI);
    double* redD    = (double*)(smem + OFF_REDD);
    float*  e2Sh    = (float*)(smem + OFF_E2);
    float*  r2Sh    = (float*)(smem + OFF_R2);
    int*    bestI   = (int*)(smem + OFF_BEST);
    int*    candTok = (int*)(smem + OFF_CTOK);
    int*    candCnt = (int*)(smem + OFF_CCNT);
    const uint32_t bbufA = (uint32_t)__cvta_generic_to_shared(smem + OFF_BBUF);
    const uint32_t mbarA = (uint32_t)__cvta_generic_to_shared(smem + OFF_MBAR);

    const int tid  = threadIdx.x;
    const int wid  = tid >> 5;
    const int lane = tid & 31;
    const int wm   = wid & 3;    // M group: rows [wm*32, wm*32+32)
    const int wn   = wid >> 2;   // N quarter: codes [wn*32, wn*32+32) per chunk
    const int g    = lane >> 2;
    const int tg2  = (lane & 3) * 2;
    const long long tokenBase = (long long)blockIdx.x * TM;
    const float* Xblk = X + tokenBase * DDIM;
    const float INF = __int_as_float(0x7f800000);

    if (tid == 0) {
        mbar_init(mbarA + 0, 1);
        mbar_init(mbarA + 8, 1);
        mbar_init(mbarA + 16, 1);
        FENCE_PROXY_ASYNC();
    }

    // ---- load X tile -----------------------------------------------------
    for (int idx = tid; idx < TM * (DDIM / 4); idx += THREADS) {
        int t = idx >> 6, dq = (idx & 63) << 2;
        *(float4*)(Rsh + t * RS + dq) = *(const float4*)(Xblk + (long long)t * DDIM + dq);
    }
    __syncthreads();

    // ---- initial r2 (fp64 -> fp32) ---------------------------------------
    {
        int t = tid >> 2, h = tid & 3;
        const float* rr = Rsh + t * RS + h * 64;
        double s = 0.0;
        for (int k = 0; k < 64; k++) { float f = rr[k]; s += (double)f * f; }
        redD[tid] = s;
        __syncthreads();
        if (!h) r2Sh[t] = (float)(redD[tid] + redD[tid + 1] + redD[tid + 2] + redD[tid + 3]);
    }
    __syncthreads();

    double commitAcc = 0.0;
    uint32_t ph0 = 0, ph1 = 0, ph2 = 0;   // per-stage mbarrier parity

    for (int lvl = 0; lvl < MLVL; lvl++) {
        // ---- level setup: e2, candCnt, A s8 fragments --------------------
        if (tid == 0) *candCnt = 0;
        for (int i = tid; i < KCODES; i += THREADS) e2Sh[i] = g_e2[lvl * KCODES + i];
        for (int idx = tid; idx < 8 * 8 * 32; idx += THREADS) {
            int mt = idx >> 8, kb = (idx >> 5) & 7, ln = idx & 31;
            int g2 = ln >> 2, tg = ln & 3;
            int row0 = mt * 16 + g2;
            int k0 = kb * 32 + tg * 4;
            const float* ra = Rsh + row0 * RS;
            const float* rb = Rsh + (row0 + 8) * RS;
            uint4 v;
            v.x = pk8(ra[k0],      ra[k0 + 1],  ra[k0 + 2],  ra[k0 + 3],  SA_Q);
            v.y = pk8(rb[k0],      rb[k0 + 1],  rb[k0 + 2],  rb[k0 + 3],  SA_Q);
            v.z = pk8(ra[k0 + 16], ra[k0 + 17], ra[k0 + 18], ra[k0 + 19], SA_Q);
            v.w = pk8(rb[k0 + 16], rb[k0 + 17], rb[k0 + 18], rb[k0 + 19], SA_Q);
            Af[idx] = v;
        }
        __syncthreads();   // Af ready

        float r2v[2][2];
#pragma unroll
        for (int mt = 0; mt < 2; mt++) {
            int tk = wm * 32 + mt * 16 + g;
            r2v[mt][0] = r2Sh[tk];
            r2v[mt][1] = r2Sh[tk + 8];
        }

        Top4 T[4];   // [mt*2 + rowhalf]
#pragma unroll
        for (int q = 0; q < 4; q++) {
            T[q].d0 = T[q].d1 = T[q].d2 = T[q].d3 = INF;
            T[q].i0 = T[q].i1 = T[q].i2 = T[q].i3 = 0x7fffffff;
        }

        const uint2* gb = g_cbfrag8 + (size_t)lvl * 32768;

        // ---- prologue: TMA-bulk slices 0,1 (8KB each) ---------------------
        if (tid == 0) {
            bulk_g2s(bbufA,        gb,        8192, mbarA + 0);
            bulk_g2s(bbufA + 8192, gb + 1024, 8192, mbarA + 8);
        }

        int acc[2][4][4];   // [mt][nt][c]

        for (int sl = 0; sl < 32; sl++) {
            const int cur = sl - (sl / 3) * 3;   // sl % 3
            __syncthreads();   // all warps done with stage (sl+2)%3 (iter sl-1)
            if (tid == 0 && sl + 2 < 32) {
                int nb = cur >= 1 ? cur - 1 : 2;   // (sl+2)%3
                bulk_g2s(bbufA + nb * 8192, gb + (size_t)(sl + 2) * 1024,
                         8192, mbarA + nb * 8);
            }
            if (cur == 0)      { mbar_wait(mbarA + 0,  ph0); ph0 ^= 1; }
            else if (cur == 1) { mbar_wait(mbarA + 8,  ph1); ph1 ^= 1; }
            else               { mbar_wait(mbarA + 16, ph2); ph2 ^= 1; }

            if ((sl & 3) == 0) {
#pragma unroll
                for (int mt = 0; mt < 2; mt++)
#pragma unroll
                    for (int nt = 0; nt < 4; nt++)
#pragma unroll
                        for (int c = 0; c < 4; c++) acc[mt][nt][c] = 0;
            }

#pragma unroll
            for (int kb2 = 0; kb2 < 2; kb2++) {
                int kb = (sl & 3) * 2 + kb2;
                uint4 A0 = Af[((wm * 2 + 0) * 8 + kb) * 32 + lane];
                uint4 A1 = Af[((wm * 2 + 1) * 8 + kb) * 32 + lane];
                const uint2* Bp = Bb8 + cur * 1024 + kb2 * 512 + (wn * 4) * 32 + lane;
                uint2 Bv[4];
#pragma unroll
                for (int nt = 0; nt < 4; nt++) Bv[nt] = Bp[nt * 32];
#pragma unroll
                for (int nt = 0; nt < 4; nt++) {
                    imma16832(acc[0][nt], A0, Bv[nt].x, Bv[nt].y);
                    imma16832(acc[1][nt], A1, Bv[nt].x, Bv[nt].y);
                }
            }

            // ---- per-chunk epilogue: dist + top-4 streaming ---------------
            if ((sl & 3) == 3) {
                const int nc = sl >> 2;
#pragma unroll
                for (int mt = 0; mt < 2; mt++) {
#pragma unroll
                    for (int nt = 0; nt < 4; nt++) {
                        int nbase = nc * 128 + wn * 32 + nt * 8 + tg2;
                        float2 e2p = *(const float2*)&e2Sh[nbase];
                        float b00 = r2v[mt][0] + e2p.x;
                        float b01 = r2v[mt][0] + e2p.y;
                        float b10 = r2v[mt][1] + e2p.x;
                        float b11 = r2v[mt][1] + e2p.y;
                        t4s_insert(T[mt*2+0], fmaf(M2D, (float)acc[mt][nt][0], b00), nbase);
                        t4s_insert(T[mt*2+0], fmaf(M2D, (float)acc[mt][nt][1], b01), nbase + 1);
                        t4s_insert(T[mt*2+1], fmaf(M2D, (float)acc[mt][nt][2], b10), nbase);
                        t4s_insert(T[mt*2+1], fmaf(M2D, (float)acc[mt][nt][3], b11), nbase + 1);
                    }
                }
            }
        } // slices

        __syncthreads();

        // ---- quad merge + saturation bound, publish per-quarter -----------
#pragma unroll
        for (int q = 0; q < 4; q++) {
            // lane-level truncation bound: min over quad of each lane's kept 4th
            float l4 = T[q].d3;
            l4 = fminf(l4, __shfl_xor_sync(0xffffffffu, l4, 1));
            l4 = fminf(l4, __shfl_xor_sync(0xffffffffu, l4, 2));

            float md[4] = { T[q].d0, T[q].d1, T[q].d2, T[q].d3 };
            int   mi[4] = { T[q].i0, T[q].i1, T[q].i2, T[q].i3 };
#pragma unroll
            for (int off = 1; off <= 2; off <<= 1) {
                float od[4]; int oi[4];
#pragma unroll
                for (int j = 0; j < 4; j++) {
                    od[j] = __shfl_xor_sync(0xffffffffu, md[j], off);
                    oi[j] = __shfl_xor_sync(0xffffffffu, mi[j], off);
                }
#pragma unroll
                for (int j = 0; j < 4; j++) t4_insert(md, mi, od[j], oi[j]);
            }
            if ((lane & 3) == 0) {
                int tok = wm * 32 + (q >> 1) * 16 + g + (q & 1) * 8;
                // .w carries satT = upper bound on anything truncated in this
                // quarter (quad-level md[3] or lane-level l4). satT >= global
                // best, so it can only shrink the gap (conservative -> safe).
                float satT = fminf(md[3], l4);
                htd[wn * TM + tok] = make_float4(md[0], md[1], md[2], satT);
                hti[wn * TM + tok] = make_int4(mi[0], mi[1], mi[2], mi[3]);
            }
        }
        __syncthreads();

        // ---- decision (one thread per token): top-2 over 16 + saturation --
        if (tid < TM) {
            float4 ds[4]; int4 is[4];
#pragma unroll
            for (int q = 0; q < 4; q++) { ds[q] = htd[q * TM + tid]; is[q] = hti[q * TM + tid]; }
            float d0 = INF, d1 = INF; int i0v = 0x7fffffff, i1v = 0x7fffffff;
#pragma unroll
            for (int q = 0; q < 4; q++) {
                const float* dp = &ds[q].x;
                const int*   ip = &is[q].x;
#pragma unroll
                for (int j = 0; j < 4; j++) {
                    float d = dp[j]; int i = ip[j];
                    if (d < d0 || (d == d0 && i < i0v)) {
                        d1 = d0; i1v = i0v; d0 = d; i0v = i;
                    } else if (d < d1 || (d == d1 && i < i1v)) {
                        d1 = d; i1v = i;
                    }
                }
            }
            if (d1 >= d0 + MARGIN) {
                bestI[tid] = i0v;
            } else {
                int sat = 0;
#pragma unroll
                for (int q = 0; q < 4; q++)
                    if (ds[q].w < d0 + MARGIN) sat |= 1 << q;
                int p = atomicAdd(candCnt, 1);
                candTok[p] = tid | (sat << 16);
            }
        }
        __syncthreads();

        // ---- rescue: exact fp32 over 16-union (+ saturated-quarter scans) -
        {
            int cnt = *candCnt;
            for (int e = wid; e < cnt; e += 16) {
                int ent = candTok[e];
                int tok = ent & 0xffff, sat = ent >> 16;
                float r2t = r2Sh[tok];
                const float* rrow = Rsh + tok * RS + lane * 8;
                float bd = INF; int bi = 0x7fffffff;
#pragma unroll
                for (int q = 0; q < 4; q++) {
                    int4 cs = hti[q * TM + tok];
                    const int* ip = &cs.x;
#pragma unroll
                    for (int j = 0; j < 4; j++) {
                        int idx = ip[j];
                        if (idx >= KCODES) continue;
                        const float* crow = CB + ((size_t)lvl * KCODES + idx) * DDIM + lane * 8;
                        float p = 0.f;
#pragma unroll
                        for (int u = 0; u < 8; u++) p = fmaf(rrow[u], crow[u], p);
#pragma unroll
                        for (int o = 16; o; o >>= 1) p += __shfl_xor_sync(0xffffffffu, p, o);
                        float dd = fmaf(-2.f, p, r2t + e2Sh[idx]);
                        if (dd < bd || (dd == bd && idx < bi)) { bd = dd; bi = idx; }
                    }
                }
                // full exact scan of saturated quarters (256 codes each; rare)
                for (int q = 0; q < 4; q++) {
                    if (!((sat >> q) & 1)) continue;
                    for (int nc2 = 0; nc2 < 8; nc2++) {
                        for (int j = 0; j < 32; j++) {
                            int idx = nc2 * 128 + q * 32 + j;
                            const float* crow = CB + ((size_t)lvl * KCODES + idx) * DDIM + lane * 8;
                            float p = 0.f;
#pragma unroll
                            for (int u = 0; u < 8; u++) p = fmaf(rrow[u], crow[u], p);
#pragma unroll
                            for (int o = 16; o; o >>= 1) p += __shfl_xor_sync(0xffffffffu, p, o);
                            float dd = fmaf(-2.f, p, r2t + e2Sh[idx]);
                            if (dd < bd || (dd == bd && idx < bi)) { bd = dd; bi = idx; }
                        }
                    }
                }
                if (lane == 0) bestI[tok] = bi;
            }
        }
        __syncthreads();

        // ---- residual update + new r2 + commit (4 threads / token) --------
        {
            int t = tid >> 2, h = tid & 3;
            int b = bestI[t];
            const float* qv = CB + ((size_t)lvl * KCODES + b) * DDIM + h * 64;
            float* rr = Rsh + t * RS + h * 64;
            double ss = 0.0;
            for (int k = 0; k < 64; k += 4) {
                float4 q4 = *(const float4*)(qv + k);
                float n0 = rr[k]     - q4.x;
                float n1 = rr[k + 1] - q4.y;
                float n2 = rr[k + 2] - q4.z;
                float n3 = rr[k + 3] - q4.w;
                rr[k] = n0; rr[k + 1] = n1; rr[k + 2] = n2; rr[k + 3] = n3;
                ss += (double)n0 * n0 + (double)n1 * n1
                    + (double)n2 * n2 + (double)n3 * n3;
            }
            redD[tid] = ss;
            commitAcc += ss;
            __syncthreads();
            if (!h) r2Sh[t] = (float)(redD[tid] + redD[tid + 1] + redD[tid + 2] + redD[tid + 3]);
        }
        __syncthreads();
    } // levels

    // ---- y = x - r_final ---------------------------------------------------
    for (int idx = tid; idx < TM * (DDIM / 4); idx += THREADS) {
        int t = idx >> 6, dq = (idx & 63) << 2;
        float4 xv = *(const float4*)(Xblk + (long long)t * DDIM + dq);
        const float* rr = Rsh + t * RS + dq;
        float4 y;
        y.x = xv.x - rr[0]; y.y = xv.y - rr[1];
        y.z = xv.z - rr[2]; y.w = xv.w - rr[3];
        *(float4*)(Y + (tokenBase + t) * DDIM + dq) = y;
    }

    // ---- deterministic per-block commit partial ----------------------------
    redD[tid] = commitAcc;
    for (int s = THREADS / 2; s > 0; s >>= 1) {
        __syncthreads();
        if (tid < s) redD[tid] += redD[tid + s];
    }
    if (tid == 0) g_commitPartial[blockIdx.x] = redD[0];
}

// ---------------------------------------------------------------------------
__global__ void finalize_kernel(float* __restrict__ Y, int out_size) {
    __shared__ double sd[NBLOCKS];
    int tid = threadIdx.x;
    sd[tid] = g_commitPartial[tid];
    for (int s = NBLOCKS / 2; s > 0; s >>= 1) {
        __syncthreads();
        if (tid < s) sd[tid] += sd[tid + s];
    }
    if (tid == 0) {
        double mean = sd[0] / (double)((long long)NTOK * DDIM);
        float commit = (float)(0.25 * mean);
        long long numel = (long long)NTOK * DDIM;
        for (long long j = numel; j < (long long)out_size; j++) Y[j] = commit;
    }
}

extern "C" void kernel_launch(void* const* d_in, const int* in_sizes, int n_in,
                              void* d_out, int out_size) {
    const float* X  = (const float*)d_in[0];
    const float* CB = (const float*)d_in[1];
    float* Y = (float*)d_out;

    cudaFuncSetAttribute(rvq_mma, cudaFuncAttributeMaxDynamicSharedMemorySize,
                         SMEM_TOTAL);

    e2_kernel<<<(MLVL * KCODES * 32 + 255) / 256, 256>>>(CB);
    prep_cb8<<<(MLVL * 64 * 16 * 32 + 255) / 256, 256>>>(CB);
    rvq_mma<<<NBLOCKS, THREADS, SMEM_TOTAL>>>(X, CB, Y);
    finalize_kernel<<<1, NBLOCKS>>>(Y, out_size);
}

// round 11
// speedup vs baseline: 1.6325x; 1.6325x over previous
#include <cuda_runtime.h>
#include <cuda_bf16.h>
#include <cstdint>

// Problem constants
#define NTOK    65536
#define DDIM    256
#define KCODES  1024
#define MLVL    4
#define THREADS 512
#define RS      260            // fp32 residual row stride (floats)
#define MARGIN  4e-4f
// Mixed tiling: 432 big tiles (128 tok) + 160 small tiles (64 tok) = 592 = 4*148
#define NBIG    432
#define NSMALL  160
#define GRID    (NBIG + NSMALL)

// SMEM byte offsets (dynamic smem, total 228880) — identical to round-5 best
#define OFF_RSH    0            // 133120: [128][260] fp32 residual
#define OFF_AFRAG  133120       // 65536:  A fragments [mt8][ks16][lane32] uint4
#define OFF_BBUF   198656       // 24576:  3 x 8KB B slices (ring)
// Overlays inside BBUF (dead while ring unused; barrier-separated):
#define OFF_HTD    198656       // float4 topDist[seg][tok] (8192)
#define OFF_HTI    206848       // int4   topIdx [seg][tok] (8192)
#define OFF_CIDX   215040       // int4   candIdx[128]      (2048)
#define OFF_REDD   217088       // double redD[512]         (4096)
#define OFF_E2     223232       // 4096
#define OFF_R2     227328       // 512
#define OFF_BEST   227840       // 512
#define OFF_CTOK   228352       // 512
#define OFF_CCNT   228864       // 16
#define SMEM_TOTAL 228880

__device__ float  g_e2[MLVL * KCODES];
__device__ double g_commitPartial[GRID];
// B fragments: [lvl][slice(64)][512 x uint4]  (slice = nc*8 + kb, 8KB each)
__device__ uint4  g_cbfrag[MLVL * 64 * 512];

static __device__ __forceinline__ uint32_t pkbf(float a, float b) {
    __nv_bfloat162 h = __floats2bfloat162_rn(a, b);
    return *reinterpret_cast<uint32_t*>(&h);
}
static __device__ __forceinline__ void mma16816(float* c, const uint4& A,
                                                uint32_t b0, uint32_t b1) {
    asm volatile(
        "mma.sync.aligned.m16n8k16.row.col.f32.bf16.bf16.f32 "
        "{%0,%1,%2,%3}, {%4,%5,%6,%7}, {%8,%9}, {%0,%1,%2,%3};"
        : "+f"(c[0]), "+f"(c[1]), "+f"(c[2]), "+f"(c[3])
        : "r"(A.x), "r"(A.y), "r"(A.z), "r"(A.w), "r"(b0), "r"(b1));
}
static __device__ __forceinline__ void cpasync16(void* dst, const void* src) {
    uint32_t d = (uint32_t)__cvta_generic_to_shared(dst);
    asm volatile("cp.async.cg.shared.global [%0], [%1], 16;" :: "r"(d), "l"(src));
}
#define CP_COMMIT() asm volatile("cp.async.commit_group;")
#define CP_WAIT(n)  asm volatile("cp.async.wait_group %0;" :: "n"(n))

// ---------------------------------------------------------------------------
// Merged prep: per-thread codebook fragment pack + per-warp e2 row.
// grid 512 x 256 = 131072 threads = 4096 warps (one per codebook row).
// ---------------------------------------------------------------------------
__global__ void prep_all(const float* __restrict__ cb) {
    int id = blockIdx.x * blockDim.x + threadIdx.x;
    // --- fragment pack (one uint4 per thread) ---
    if (id < MLVL * 64 * 512) {
        int u    = id & 511;
        int half = u >> 8;
        int nt   = (u >> 5) & 7;
        int lane = u & 31;
        int s    = (id >> 9) & 63;
        int lvl  = id >> 15;
        int nc = s >> 3, kb = s & 7;
        int n  = nc * 128 + half * 64 + nt * 8 + (lane >> 2);
        int k0 = kb * 32 + (lane & 3) * 2;
        const float* row = cb + ((size_t)lvl * KCODES + n) * DDIM;
        uint4 v;
        v.x = pkbf(row[k0],      row[k0 + 1]);
        v.y = pkbf(row[k0 + 8],  row[k0 + 9]);
        v.z = pkbf(row[k0 + 16], row[k0 + 17]);
        v.w = pkbf(row[k0 + 24], row[k0 + 25]);
        g_cbfrag[id] = v;
    }
    // --- e2 (one warp per codebook row, fp64 accumulate) ---
    int warp = id >> 5;
    int lane = id & 31;
    if (warp < MLVL * KCODES) {
        const float* row = cb + (size_t)warp * DDIM;
        double s = 0.0;
#pragma unroll
        for (int m = 0; m < DDIM / 32; m++) {
            float v = row[lane + 32 * m];
            s += (double)v * (double)v;
        }
#pragma unroll
        for (int off = 16; off; off >>= 1) s += __shfl_xor_sync(0xffffffffu, s, off);
        if (lane == 0) g_e2[warp] = (float)s;
    }
}

// ---------------------------------------------------------------------------
struct Top3 { float d0, d1, d2; int i0, i1, i2; };
static __device__ __forceinline__ void t3_insert(Top3& T, float d, int idx) {
    if (d < T.d2) {
        if (d < T.d1) {
            T.d2 = T.d1; T.i2 = T.i1;
            if (d < T.d0) { T.d1 = T.d0; T.i1 = T.i0; T.d0 = d; T.i0 = idx; }
            else          { T.d1 = d;    T.i1 = idx; }
        } else { T.d2 = d; T.i2 = idx; }
    }
}
static __device__ __forceinline__ void t4_insert(float* d, int* i, float nd, int ni) {
    bool l3 = (nd < d[3]) || (nd == d[3] && ni < i[3]);
    if (!l3) return;
    bool l2 = (nd < d[2]) || (nd == d[2] && ni < i[2]);
    bool l1 = (nd < d[1]) || (nd == d[1] && ni < i[1]);
    bool l0 = (nd < d[0]) || (nd == d[0] && ni < i[0]);
    if (l0)      { d[3]=d[2]; i[3]=i[2]; d[2]=d[1]; i[2]=i[1]; d[1]=d[0]; i[1]=i[0]; d[0]=nd; i[0]=ni; }
    else if (l1) { d[3]=d[2]; i[3]=i[2]; d[2]=d[1]; i[2]=i[1]; d[1]=nd; i[1]=ni; }
    else if (l2) { d[3]=d[2]; i[3]=i[2]; d[2]=nd; i[2]=ni; }
    else         { d[3]=nd; i[3]=ni; }
}

// ---------------------------------------------------------------------------
// Main fused residual-VQ kernel. Round-5 chassis (3-stage cp.async ring,
// bf16 HMMA screen + margin + exact-fp32 rescue), dual tile size:
//   big  (bid <  NBIG): 128 tokens, warp tile 16 tok x 64 codes (wn in 0..1)
//   small(bid >= NBIG):  64 tokens, warp tile 16 tok x 32 codes (wn in 0..3)
// ---------------------------------------------------------------------------
__global__ __launch_bounds__(THREADS, 1)
void rvq_mma(const float* __restrict__ X, const float* __restrict__ CB,
             float* __restrict__ Y) {
    extern __shared__ char smem[];
    float*  Rsh     = (float*)(smem + OFF_RSH);
    uint4*  Af      = (uint4*)(smem + OFF_AFRAG);
    uint4*  Bb      = (uint4*)(smem + OFF_BBUF);
    float4* htd     = (float4*)(smem + OFF_HTD);
    int4*   hti     = (int4*)(smem + OFF_HTI);
    int4*   candIdx = (int4*)(smem + OFF_CIDX);
    double* redD    = (double*)(smem + OFF_REDD);
    float*  e2Sh    = (float*)(smem + OFF_E2);
    float*  r2Sh    = (float*)(smem + OFF_R2);
    int*    bestI   = (int*)(smem + OFF_BEST);
    int*    candTok = (int*)(smem + OFF_CTOK);
    int*    candCnt = (int*)(smem + OFF_CCNT);

    const int  tid   = threadIdx.x;
    const int  wid   = tid >> 5;
    const int  lane  = tid & 31;
    const bool small = (blockIdx.x >= NBIG);
    const int  TMloc = small ? 64 : 128;
    const int  wm    = small ? (wid & 3) : (wid & 7);   // 16-token M tile
    const int  wn    = small ? (wid >> 2) : (wid >> 3); // N segment
    const int  NTt   = small ? 4 : 8;                   // ntiles per warp
    const int  NH    = small ? 4 : 2;                   // segments per token
    // B fragment base offset for this warp's code segment within a slice
    const int  bOff  = small ? ((wn >> 1) * 256 + (wn & 1) * 128) : (wn * 256);
    const int  cSeg  = small ? 32 : 64;                 // codes per segment
    const int  g     = lane >> 2;
    const int  tg2   = (lane & 3) * 2;
    const long long tokenBase = small
        ? (long long)NBIG * 128 + (long long)(blockIdx.x - NBIG) * 64
        : (long long)blockIdx.x * 128;
    const float* Xblk = X + tokenBase * DDIM;
    const float INF = __int_as_float(0x7f800000);

    // ---- load X tile -----------------------------------------------------
    for (int idx = tid; idx < TMloc * (DDIM / 4); idx += THREADS) {
        int t = idx >> 6, dq = (idx & 63) << 2;
        *(float4*)(Rsh + t * RS + dq) = *(const float4*)(Xblk + (long long)t * DDIM + dq);
    }
    __syncthreads();

    // ---- initial r2 (fp64 -> fp32), redD overlays ring (no B traffic yet)
    {
        int t = tid >> 2, h = tid & 3;
        if (t < TMloc) {
            const float* rr = Rsh + t * RS + h * 64;
            double s = 0.0;
            for (int k = 0; k < 64; k++) { float f = rr[k]; s += (double)f * f; }
            redD[tid] = s;
        }
        __syncthreads();
        if (t < TMloc && !h)
            r2Sh[t] = (float)(redD[tid] + redD[tid + 1] + redD[tid + 2] + redD[tid + 3]);
    }
    __syncthreads();

    double commitAcc = 0.0;

    for (int lvl = 0; lvl < MLVL; lvl++) {
        // ---- level setup: e2, candCnt, A fragments (bf16) ----------------
        if (tid == 0) *candCnt = 0;
        for (int i = tid; i < KCODES; i += THREADS) e2Sh[i] = g_e2[lvl * KCODES + i];
        for (int idx = tid; idx < (TMloc / 16) * 16 * 32; idx += THREADS) {
            int mt = idx >> 9, ks = (idx >> 5) & 15, ln = idx & 31;
            int m0 = mt * 16 + (ln >> 2);
            int k0 = ks * 16 + (ln & 3) * 2;
            const float* ra = Rsh + m0 * RS;
            const float* rb = Rsh + (m0 + 8) * RS;
            uint4 v;
            v.x = pkbf(ra[k0],     ra[k0 + 1]);
            v.y = pkbf(rb[k0],     rb[k0 + 1]);
            v.z = pkbf(ra[k0 + 8], ra[k0 + 9]);
            v.w = pkbf(rb[k0 + 8], rb[k0 + 9]);
            Af[idx] = v;
        }
        __syncthreads();   // Af ready; ring overlays dead below

        const float r2a = r2Sh[wm * 16 + g];
        const float r2b = r2Sh[wm * 16 + g + 8];

        Top3 T[2];
#pragma unroll
        for (int q = 0; q < 2; q++) { T[q].d0 = T[q].d1 = T[q].d2 = INF; T[q].i0 = T[q].i1 = T[q].i2 = 0x7fffffff; }

        const uint4* gb = g_cbfrag + (size_t)lvl * 64 * 512;

        // ---- prologue: prefetch stages 0,1 (one 16B per thread each) -----
        cpasync16(Bb + 0 * 512 + tid, gb + 0 * 512 + tid);
        CP_COMMIT();
        cpasync16(Bb + 1 * 512 + tid, gb + 1 * 512 + tid);
        CP_COMMIT();

        float acc[8][4];
        int cur = 0;

        for (int sl = 0; sl < 64; sl++) {
            const int kb = sl & 7;
            CP_WAIT(1);        // stage sl landed
            __syncthreads();   // visible to all; all done with buf (sl-1)%3
            if (sl + 2 < 64) {
                int nb = cur == 0 ? 2 : cur - 1;   // (sl+2)%3
                cpasync16(Bb + nb * 512 + tid, gb + (size_t)(sl + 2) * 512 + tid);
            }
            CP_COMMIT();       // unconditional: uniform group indexing

            if (kb == 0) {
                for (int nt = 0; nt < NTt; nt++)
#pragma unroll
                    for (int c = 0; c < 4; c++) acc[nt][c] = 0.f;
            }

            uint4 A0 = Af[(wm * 16 + kb * 2 + 0) * 32 + lane];
            uint4 A1 = Af[(wm * 16 + kb * 2 + 1) * 32 + lane];
            const uint4* Bp = Bb + cur * 512 + bOff + lane;
            if (small) {
                uint4 Bv[4];
#pragma unroll
                for (int nt = 0; nt < 4; nt++) Bv[nt] = Bp[nt * 32];
#pragma unroll
                for (int nt = 0; nt < 4; nt++) mma16816(acc[nt], A0, Bv[nt].x, Bv[nt].y);
#pragma unroll
                for (int nt = 0; nt < 4; nt++) mma16816(acc[nt], A1, Bv[nt].z, Bv[nt].w);
            } else {
                uint4 Bv[8];
#pragma unroll
                for (int nt = 0; nt < 8; nt++) Bv[nt] = Bp[nt * 32];
#pragma unroll
                for (int nt = 0; nt < 8; nt++) mma16816(acc[nt], A0, Bv[nt].x, Bv[nt].y);
#pragma unroll
                for (int nt = 0; nt < 8; nt++) mma16816(acc[nt], A1, Bv[nt].z, Bv[nt].w);
            }

            // ---- per-chunk epilogue: dist + top-3 streaming --------------
            if (kb == 7) {
                const int nc = sl >> 3;
                for (int nt = 0; nt < NTt; nt++) {
                    int nbase = nc * 128 + wn * cSeg + nt * 8 + tg2;
                    float2 e2p = *(const float2*)&e2Sh[nbase];
                    t3_insert(T[0], fmaf(-2.f, acc[nt][0], r2a + e2p.x), nbase);
                    t3_insert(T[0], fmaf(-2.f, acc[nt][1], r2a + e2p.y), nbase + 1);
                    t3_insert(T[1], fmaf(-2.f, acc[nt][2], r2b + e2p.x), nbase);
                    t3_insert(T[1], fmaf(-2.f, acc[nt][3], r2b + e2p.y), nbase + 1);
                }
            }
            cur = cur == 2 ? 0 : cur + 1;
        } // slices

        __syncthreads();   // compute done before htd/hti overlay ring

        // ---- quad merge, publish per-(segment,token) top-4 to SMEM -------
#pragma unroll
        for (int q = 0; q < 2; q++) {
            float md[4] = { T[q].d0, T[q].d1, T[q].d2, INF };
            int   mi[4] = { T[q].i0, T[q].i1, T[q].i2, 0x7fffffff };
#pragma unroll
            for (int off = 1; off <= 2; off <<= 1) {
                float od[4]; int oi[4];
#pragma unroll
                for (int j = 0; j < 4; j++) {
                    od[j] = __shfl_xor_sync(0xffffffffu, md[j], off);
                    oi[j] = __shfl_xor_sync(0xffffffffu, mi[j], off);
                }
#pragma unroll
                for (int j = 0; j < 4; j++) t4_insert(md, mi, od[j], oi[j]);
            }
            if ((lane & 3) == 0) {
                int tok = wm * 16 + g + q * 8;
                htd[wn * TMloc + tok] = make_float4(md[0], md[1], md[2], md[3]);
                hti[wn * TMloc + tok] = make_int4(mi[0], mi[1], mi[2], mi[3]);
            }
        }
        __syncthreads();

        // ---- cross-segment merge + decision (one thread per token) -------
        if (tid < TMloc) {
            float4 d0 = htd[tid];  int4 i0 = hti[tid];
            float md[4] = { d0.x, d0.y, d0.z, d0.w };
            int   mi[4] = { i0.x, i0.y, i0.z, i0.w };
            for (int h = 1; h < NH; h++) {
                float4 dh = htd[h * TMloc + tid];  int4 ih = hti[h * TMloc + tid];
                t4_insert(md, mi, dh.x, ih.x);
                t4_insert(md, mi, dh.y, ih.y);
                t4_insert(md, mi, dh.z, ih.z);
                t4_insert(md, mi, dh.w, ih.w);
            }
            if (md[1] >= md[0] + MARGIN) {
                bestI[tid] = mi[0];
            } else {
                int p = atomicAdd(candCnt, 1);
                candTok[p] = tid;
                candIdx[tid] = make_int4(mi[0], mi[1], mi[2], mi[3]);
            }
        }
        __syncthreads();

        // ---- rescue: exact fp32 dots for flagged tokens (warp per entry) -
        {
            int cnt = *candCnt;
            for (int e = wid; e < cnt; e += 16) {
                int tok = candTok[e];
                int4 cs = candIdx[tok];
                float r2t = r2Sh[tok];
                const float* rrow = Rsh + tok * RS + lane * 8;
                float bd = INF; int bi = 0x7fffffff;
#pragma unroll
                for (int j = 0; j < 4; j++) {
                    int idx = (&cs.x)[j];
                    const float* crow = CB + ((size_t)lvl * KCODES + idx) * DDIM + lane * 8;
                    float p = 0.f;
#pragma unroll
                    for (int u = 0; u < 8; u++) p = fmaf(rrow[u], crow[u], p);
#pragma unroll
                    for (int o = 16; o; o >>= 1) p += __shfl_xor_sync(0xffffffffu, p, o);
                    float dd = fmaf(-2.f, p, r2t + e2Sh[idx]);
                    if (dd < bd || (dd == bd && idx < bi)) { bd = dd; bi = idx; }
                }
                if (lane == 0) bestI[tok] = bi;
            }
        }
        __syncthreads();

        // ---- residual update + new r2 + commit (4 threads / token) -------
        {
            int t = tid >> 2, h = tid & 3;
            if (t < TMloc) {
                int b = bestI[t];
                const float* qv = CB + ((size_t)lvl * KCODES + b) * DDIM + h * 64;
                float* rr = Rsh + t * RS + h * 64;
                double ss = 0.0;
                for (int k = 0; k < 64; k += 4) {
                    float4 q4 = *(const float4*)(qv + k);
                    float n0 = rr[k]     - q4.x;
                    float n1 = rr[k + 1] - q4.y;
                    float n2 = rr[k + 2] - q4.z;
                    float n3 = rr[k + 3] - q4.w;
                    rr[k] = n0; rr[k + 1] = n1; rr[k + 2] = n2; rr[k + 3] = n3;
                    ss += (double)n0 * n0 + (double)n1 * n1
                        + (double)n2 * n2 + (double)n3 * n3;
                }
                redD[tid] = ss;
                commitAcc += ss;
            }
            __syncthreads();
            if (t < TMloc && !h)
                r2Sh[t] = (float)(redD[tid] + redD[tid + 1] + redD[tid + 2] + redD[tid + 3]);
        }
        __syncthreads();
    } // levels

    // ---- y = x - r_final ---------------------------------------------------
    for (int idx = tid; idx < TMloc * (DDIM / 4); idx += THREADS) {
        int t = idx >> 6, dq = (idx & 63) << 2;
        float4 xv = *(const float4*)(Xblk + (long long)t * DDIM + dq);
        const float* rr = Rsh + t * RS + dq;
        float4 y;
        y.x = xv.x - rr[0]; y.y = xv.y - rr[1];
        y.z = xv.z - rr[2]; y.w = xv.w - rr[3];
        *(float4*)(Y + (tokenBase + t) * DDIM + dq) = y;
    }

    // ---- deterministic per-block commit partial ----------------------------
    redD[tid] = commitAcc;
    for (int s = THREADS / 2; s > 0; s >>= 1) {
        __syncthreads();
        if (tid < s) redD[tid] += redD[tid + s];
    }
    if (tid == 0) g_commitPartial[blockIdx.x] = redD[0];
}

// ---------------------------------------------------------------------------
__global__ void finalize_kernel(float* __restrict__ Y, int out_size) {
    __shared__ double sd[1024];
    int tid = threadIdx.x;
    sd[tid] = (tid < GRID) ? g_commitPartial[tid] : 0.0;
    for (int s = 512; s > 0; s >>= 1) {
        __syncthreads();
        if (tid < s) sd[tid] += sd[tid + s];
    }
    if (tid == 0) {
        double mean = sd[0] / (double)((long long)NTOK * DDIM);
        float commit = (float)(0.25 * mean);
        long long numel = (long long)NTOK * DDIM;
        for (long long j = numel; j < (long long)out_size; j++) Y[j] = commit;
    }
}

extern "C" void kernel_launch(void* const* d_in, const int* in_sizes, int n_in,
                              void* d_out, int out_size) {
    const float* X  = (const float*)d_in[0];
    const float* CB = (const float*)d_in[1];
    float* Y = (float*)d_out;

    cudaFuncSetAttribute(rvq_mma, cudaFuncAttributeMaxDynamicSharedMemorySize,
                         SMEM_TOTAL);

    prep_all<<<512, 256>>>(CB);
    rvq_mma<<<GRID, THREADS, SMEM_TOTAL>>>(X, CB, Y);
    finalize_kernel<<<1, 1024>>>(Y, out_size);
}

// round 12
// speedup vs baseline: 2.6113x; 1.5996x over previous
#include <cuda_runtime.h>
#include <cuda_bf16.h>
#include <cstdint>

// Problem constants
#define NTOK    65536
#define DDIM    256
#define KCODES  1024
#define MLVL    4
#define THREADS 512
#define RS      260            // fp32 residual row stride (floats)
#define MARGIN  4e-4f
// Mixed tiling: 432 big tiles (128 tok) + 160 small tiles (64 tok) = 592 = 4*148
#define NBIG    432
#define NSMALL  160
#define GRID    (NBIG + NSMALL)

// SMEM byte offsets (dynamic smem, total 228880) — identical to round-5 best
#define OFF_RSH    0            // 133120: [128][260] fp32 residual
#define OFF_AFRAG  133120       // 65536:  A fragments [mt8][ks16][lane32] uint4
#define OFF_BBUF   198656       // 24576:  3 x 8KB B slices (ring)
// Overlays inside BBUF (dead while ring unused; barrier-separated):
#define OFF_HTD    198656       // float4 topDist[seg][tok] (8192)
#define OFF_HTI    206848       // int4   topIdx [seg][tok] (8192)
#define OFF_CIDX   215040       // int4   candIdx[128]      (2048)
#define OFF_REDD   217088       // double redD[512]         (4096)
#define OFF_E2     223232       // 4096
#define OFF_R2     227328       // 512
#define OFF_BEST   227840       // 512
#define OFF_CTOK   228352       // 512
#define OFF_CCNT   228864       // 16
#define SMEM_TOTAL 228880

__device__ float  g_e2[MLVL * KCODES];
__device__ double g_commitPartial[GRID];
// B fragments: [lvl][slice(64)][512 x uint4]  (slice = nc*8 + kb, 8KB each)
__device__ uint4  g_cbfrag[MLVL * 64 * 512];

static __device__ __forceinline__ uint32_t pkbf(float a, float b) {
    __nv_bfloat162 h = __floats2bfloat162_rn(a, b);
    return *reinterpret_cast<uint32_t*>(&h);
}
static __device__ __forceinline__ void mma16816(float* c, const uint4& A,
                                                uint32_t b0, uint32_t b1) {
    asm volatile(
        "mma.sync.aligned.m16n8k16.row.col.f32.bf16.bf16.f32 "
        "{%0,%1,%2,%3}, {%4,%5,%6,%7}, {%8,%9}, {%0,%1,%2,%3};"
        : "+f"(c[0]), "+f"(c[1]), "+f"(c[2]), "+f"(c[3])
        : "r"(A.x), "r"(A.y), "r"(A.z), "r"(A.w), "r"(b0), "r"(b1));
}
static __device__ __forceinline__ void cpasync16(void* dst, const void* src) {
    uint32_t d = (uint32_t)__cvta_generic_to_shared(dst);
    asm volatile("cp.async.cg.shared.global [%0], [%1], 16;" :: "r"(d), "l"(src));
}
#define CP_COMMIT() asm volatile("cp.async.commit_group;")
#define CP_WAIT(n)  asm volatile("cp.async.wait_group %0;" :: "n"(n))

// ---------------------------------------------------------------------------
// Merged prep: per-thread codebook fragment pack + per-warp e2 row.
// ---------------------------------------------------------------------------
__global__ void prep_all(const float* __restrict__ cb) {
    int id = blockIdx.x * blockDim.x + threadIdx.x;
    if (id < MLVL * 64 * 512) {
        int u    = id & 511;
        int half = u >> 8;
        int nt   = (u >> 5) & 7;
        int lane = u & 31;
        int s    = (id >> 9) & 63;
        int lvl  = id >> 15;
        int nc = s >> 3, kb = s & 7;
        int n  = nc * 128 + half * 64 + nt * 8 + (lane >> 2);
        int k0 = kb * 32 + (lane & 3) * 2;
        const float* row = cb + ((size_t)lvl * KCODES + n) * DDIM;
        uint4 v;
        v.x = pkbf(row[k0],      row[k0 + 1]);
        v.y = pkbf(row[k0 + 8],  row[k0 + 9]);
        v.z = pkbf(row[k0 + 16], row[k0 + 17]);
        v.w = pkbf(row[k0 + 24], row[k0 + 25]);
        g_cbfrag[id] = v;
    }
    int warp = id >> 5;
    int lane = id & 31;
    if (warp < MLVL * KCODES) {
        const float* row = cb + (size_t)warp * DDIM;
        double s = 0.0;
#pragma unroll
        for (int m = 0; m < DDIM / 32; m++) {
            float v = row[lane + 32 * m];
            s += (double)v * (double)v;
        }
#pragma unroll
        for (int off = 16; off; off >>= 1) s += __shfl_xor_sync(0xffffffffu, s, off);
        if (lane == 0) g_e2[warp] = (float)s;
    }
}

// ---------------------------------------------------------------------------
struct Top3 { float d0, d1, d2; int i0, i1, i2; };
static __device__ __forceinline__ void t3_insert(Top3& T, float d, int idx) {
    if (d < T.d2) {
        if (d < T.d1) {
            T.d2 = T.d1; T.i2 = T.i1;
            if (d < T.d0) { T.d1 = T.d0; T.i1 = T.i0; T.d0 = d; T.i0 = idx; }
            else          { T.d1 = d;    T.i1 = idx; }
        } else { T.d2 = d; T.i2 = idx; }
    }
}
static __device__ __forceinline__ void t4_insert(float* d, int* i, float nd, int ni) {
    bool l3 = (nd < d[3]) || (nd == d[3] && ni < i[3]);
    if (!l3) return;
    bool l2 = (nd < d[2]) || (nd == d[2] && ni < i[2]);
    bool l1 = (nd < d[1]) || (nd == d[1] && ni < i[1]);
    bool l0 = (nd < d[0]) || (nd == d[0] && ni < i[0]);
    if (l0)      { d[3]=d[2]; i[3]=i[2]; d[2]=d[1]; i[2]=i[1]; d[1]=d[0]; i[1]=i[0]; d[0]=nd; i[0]=ni; }
    else if (l1) { d[3]=d[2]; i[3]=i[2]; d[2]=d[1]; i[2]=i[1]; d[1]=nd; i[1]=ni; }
    else if (l2) { d[3]=d[2]; i[3]=i[2]; d[2]=nd; i[2]=ni; }
    else         { d[3]=nd; i[3]=ni; }
}

// ---------------------------------------------------------------------------
// Templated body: fully compile-time tile geometry (round-5 chassis).
//   TMLOC=128: 8 M-warps x 2 N-segments, warp tile 16 tok x 64 codes
//   TMLOC=64 : 4 M-warps x 4 N-segments, warp tile 16 tok x 32 codes
// ---------------------------------------------------------------------------
template<int TMLOC>
static __device__ __forceinline__ void rvq_body(
    const float* __restrict__ X, const float* __restrict__ CB,
    float* __restrict__ Y, char* smem, long long tokenBase) {
    constexpr int NWM  = TMLOC / 16;    // warps along M (8 or 4)
    constexpr int NSEG = 16 / NWM;      // N segments (2 or 4)
    constexpr int NTT  = 16 / NSEG;     // ntiles per warp (8 or 4)
    constexpr int CSEG = 128 / NSEG;    // codes per segment (64 or 32)

    float*  Rsh     = (float*)(smem + OFF_RSH);
    uint4*  Af      = (uint4*)(smem + OFF_AFRAG);
    uint4*  Bb      = (uint4*)(smem + OFF_BBUF);
    float4* htd     = (float4*)(smem + OFF_HTD);
    int4*   hti     = (int4*)(smem + OFF_HTI);
    int4*   candIdx = (int4*)(smem + OFF_CIDX);
    double* redD    = (double*)(smem + OFF_REDD);
    float*  e2Sh    = (float*)(smem + OFF_E2);
    float*  r2Sh    = (float*)(smem + OFF_R2);
    int*    bestI   = (int*)(smem + OFF_BEST);
    int*    candTok = (int*)(smem + OFF_CTOK);
    int*    candCnt = (int*)(smem + OFF_CCNT);

    const int tid  = threadIdx.x;
    const int wid  = tid >> 5;
    const int lane = tid & 31;
    const int wm   = wid % NWM;
    const int wn   = wid / NWM;
    const int bOff = (CSEG == 64) ? wn * 256 : ((wn >> 1) * 256 + (wn & 1) * 128);
    const int g    = lane >> 2;
    const int tg2  = (lane & 3) * 2;
    const float* Xblk = X + tokenBase * DDIM;
    const float INF = __int_as_float(0x7f800000);

    // ---- load X tile -----------------------------------------------------
    for (int idx = tid; idx < TMLOC * (DDIM / 4); idx += THREADS) {
        int t = idx >> 6, dq = (idx & 63) << 2;
        *(float4*)(Rsh + t * RS + dq) = *(const float4*)(Xblk + (long long)t * DDIM + dq);
    }
    __syncthreads();

    // ---- initial r2 (fp64 -> fp32) ---------------------------------------
    {
        int t = tid >> 2, h = tid & 3;
        if (t < TMLOC) {
            const float* rr = Rsh + t * RS + h * 64;
            double s = 0.0;
            for (int k = 0; k < 64; k++) { float f = rr[k]; s += (double)f * f; }
            redD[tid] = s;
        }
        __syncthreads();
        if (t < TMLOC && !h)
            r2Sh[t] = (float)(redD[tid] + redD[tid + 1] + redD[tid + 2] + redD[tid + 3]);
    }
    __syncthreads();

    double commitAcc = 0.0;

    for (int lvl = 0; lvl < MLVL; lvl++) {
        // ---- level setup: e2, candCnt, A fragments (bf16) ----------------
        if (tid == 0) *candCnt = 0;
        for (int i = tid; i < KCODES; i += THREADS) e2Sh[i] = g_e2[lvl * KCODES + i];
        for (int idx = tid; idx < TMLOC * 32; idx += THREADS) {
            int mt = idx >> 9, ks = (idx >> 5) & 15, ln = idx & 31;
            int m0 = mt * 16 + (ln >> 2);
            int k0 = ks * 16 + (ln & 3) * 2;
            const float* ra = Rsh + m0 * RS;
            const float* rb = Rsh + (m0 + 8) * RS;
            uint4 v;
            v.x = pkbf(ra[k0],     ra[k0 + 1]);
            v.y = pkbf(rb[k0],     rb[k0 + 1]);
            v.z = pkbf(ra[k0 + 8], ra[k0 + 9]);
            v.w = pkbf(rb[k0 + 8], rb[k0 + 9]);
            Af[idx] = v;
        }
        __syncthreads();   // Af ready; ring overlays dead below

        const float r2a = r2Sh[wm * 16 + g];
        const float r2b = r2Sh[wm * 16 + g + 8];

        Top3 T[2];
#pragma unroll
        for (int q = 0; q < 2; q++) { T[q].d0 = T[q].d1 = T[q].d2 = INF; T[q].i0 = T[q].i1 = T[q].i2 = 0x7fffffff; }

        const uint4* gb = g_cbfrag + (size_t)lvl * 64 * 512;

        // ---- prologue: prefetch stages 0,1 (one 16B per thread each) -----
        cpasync16(Bb + 0 * 512 + tid, gb + 0 * 512 + tid);
        CP_COMMIT();
        cpasync16(Bb + 1 * 512 + tid, gb + 1 * 512 + tid);
        CP_COMMIT();

        float acc[NTT][4];
        int cur = 0;

        for (int sl = 0; sl < 64; sl++) {
            const int kb = sl & 7;
            CP_WAIT(1);        // stage sl landed
            __syncthreads();   // visible to all; all done with buf (sl-1)%3
            if (sl + 2 < 64) {
                int nb = cur == 0 ? 2 : cur - 1;   // (sl+2)%3
                cpasync16(Bb + nb * 512 + tid, gb + (size_t)(sl + 2) * 512 + tid);
            }
            CP_COMMIT();       // unconditional: uniform group indexing

            if (kb == 0) {
#pragma unroll
                for (int nt = 0; nt < NTT; nt++)
#pragma unroll
                    for (int c = 0; c < 4; c++) acc[nt][c] = 0.f;
            }

            uint4 A0 = Af[(wm * 16 + kb * 2 + 0) * 32 + lane];
            uint4 A1 = Af[(wm * 16 + kb * 2 + 1) * 32 + lane];
            const uint4* Bp = Bb + cur * 512 + bOff + lane;
            uint4 Bv[NTT];
#pragma unroll
            for (int nt = 0; nt < NTT; nt++) Bv[nt] = Bp[nt * 32];
#pragma unroll
            for (int nt = 0; nt < NTT; nt++) mma16816(acc[nt], A0, Bv[nt].x, Bv[nt].y);
#pragma unroll
            for (int nt = 0; nt < NTT; nt++) mma16816(acc[nt], A1, Bv[nt].z, Bv[nt].w);

            // ---- per-chunk epilogue: dist + top-3 streaming --------------
            if (kb == 7) {
                const int nc = sl >> 3;
#pragma unroll
                for (int nt = 0; nt < NTT; nt++) {
                    int nbase = nc * 128 + wn * CSEG + nt * 8 + tg2;
                    float2 e2p = *(const float2*)&e2Sh[nbase];
                    t3_insert(T[0], fmaf(-2.f, acc[nt][0], r2a + e2p.x), nbase);
                    t3_insert(T[0], fmaf(-2.f, acc[nt][1], r2a + e2p.y), nbase + 1);
                    t3_insert(T[1], fmaf(-2.f, acc[nt][2], r2b + e2p.x), nbase);
                    t3_insert(T[1], fmaf(-2.f, acc[nt][3], r2b + e2p.y), nbase + 1);
                }
            }
            cur = cur == 2 ? 0 : cur + 1;
        } // slices

        __syncthreads();   // compute done before htd/hti overlay ring

        // ---- quad merge, publish per-(segment,token) top-4 to SMEM -------
#pragma unroll
        for (int q = 0; q < 2; q++) {
            float md[4] = { T[q].d0, T[q].d1, T[q].d2, INF };
            int   mi[4] = { T[q].i0, T[q].i1, T[q].i2, 0x7fffffff };
#pragma unroll
            for (int off = 1; off <= 2; off <<= 1) {
                float od[4]; int oi[4];
#pragma unroll
                for (int j = 0; j < 4; j++) {
                    od[j] = __shfl_xor_sync(0xffffffffu, md[j], off);
                    oi[j] = __shfl_xor_sync(0xffffffffu, mi[j], off);
                }
#pragma unroll
                for (int j = 0; j < 4; j++) t4_insert(md, mi, od[j], oi[j]);
            }
            if ((lane & 3) == 0) {
                int tok = wm * 16 + g + q * 8;
                htd[wn * TMLOC + tok] = make_float4(md[0], md[1], md[2], md[3]);
                hti[wn * TMLOC + tok] = make_int4(mi[0], mi[1], mi[2], mi[3]);
            }
        }
        __syncthreads();

        // ---- cross-segment merge + decision (one thread per token) -------
        if (tid < TMLOC) {
            float4 d0 = htd[tid];  int4 i0 = hti[tid];
            float md[4] = { d0.x, d0.y, d0.z, d0.w };
            int   mi[4] = { i0.x, i0.y, i0.z, i0.w };
#pragma unroll
            for (int h = 1; h < NSEG; h++) {
                float4 dh = htd[h * TMLOC + tid];  int4 ih = hti[h * TMLOC + tid];
                t4_insert(md, mi, dh.x, ih.x);
                t4_insert(md, mi, dh.y, ih.y);
                t4_insert(md, mi, dh.z, ih.z);
                t4_insert(md, mi, dh.w, ih.w);
            }
            if (md[1] >= md[0] + MARGIN) {
                bestI[tid] = mi[0];
            } else {
                int p = atomicAdd(candCnt, 1);
                candTok[p] = tid;
                candIdx[tid] = make_int4(mi[0], mi[1], mi[2], mi[3]);
            }
        }
        __syncthreads();

        // ---- rescue: exact fp32 dots for flagged tokens (warp per entry) -
        {
            int cnt = *candCnt;
            for (int e = wid; e < cnt; e += 16) {
                int tok = candTok[e];
                int4 cs = candIdx[tok];
                float r2t = r2Sh[tok];
                const float* rrow = Rsh + tok * RS + lane * 8;
                float bd = INF; int bi = 0x7fffffff;
#pragma unroll
                for (int j = 0; j < 4; j++) {
                    int idx = (&cs.x)[j];
                    const float* crow = CB + ((size_t)lvl * KCODES + idx) * DDIM + lane * 8;
                    float p = 0.f;
#pragma unroll
                    for (int u = 0; u < 8; u++) p = fmaf(rrow[u], crow[u], p);
#pragma unroll
                    for (int o = 16; o; o >>= 1) p += __shfl_xor_sync(0xffffffffu, p, o);
                    float dd = fmaf(-2.f, p, r2t + e2Sh[idx]);
                    if (dd < bd || (dd == bd && idx < bi)) { bd = dd; bi = idx; }
                }
                if (lane == 0) bestI[tok] = bi;
            }
        }
        __syncthreads();

        // ---- residual update + new r2 + commit (4 threads / token) -------
        {
            int t = tid >> 2, h = tid & 3;
            if (t < TMLOC) {
                int b = bestI[t];
                const float* qv = CB + ((size_t)lvl * KCODES + b) * DDIM + h * 64;
                float* rr = Rsh + t * RS + h * 64;
                double ss = 0.0;
                for (int k = 0; k < 64; k += 4) {
                    float4 q4 = *(const float4*)(qv + k);
                    float n0 = rr[k]     - q4.x;
                    float n1 = rr[k + 1] - q4.y;
                    float n2 = rr[k + 2] - q4.z;
                    float n3 = rr[k + 3] - q4.w;
                    rr[k] = n0; rr[k + 1] = n1; rr[k + 2] = n2; rr[k + 3] = n3;
                    ss += (double)n0 * n0 + (double)n1 * n1
                        + (double)n2 * n2 + (double)n3 * n3;
                }
                redD[tid] = ss;
                commitAcc += ss;
            }
            __syncthreads();
            if (t < TMLOC && !h)
                r2Sh[t] = (float)(redD[tid] + redD[tid + 1] + redD[tid + 2] + redD[tid + 3]);
        }
        __syncthreads();
    } // levels

    // ---- y = x - r_final ---------------------------------------------------
    for (int idx = tid; idx < TMLOC * (DDIM / 4); idx += THREADS) {
        int t = idx >> 6, dq = (idx & 63) << 2;
        float4 xv = *(const float4*)(Xblk + (long long)t * DDIM + dq);
        const float* rr = Rsh + t * RS + dq;
        float4 y;
        y.x = xv.x - rr[0]; y.y = xv.y - rr[1];
        y.z = xv.z - rr[2]; y.w = xv.w - rr[3];
        *(float4*)(Y + (tokenBase + t) * DDIM + dq) = y;
    }

    // ---- deterministic per-block commit partial ----------------------------
    redD[tid] = commitAcc;
    for (int s = THREADS / 2; s > 0; s >>= 1) {
        __syncthreads();
        if (tid < s) redD[tid] += redD[tid + s];
    }
    if (tid == 0) g_commitPartial[blockIdx.x] = redD[0];
}

// ---------------------------------------------------------------------------
__global__ __launch_bounds__(THREADS, 1)
void rvq_mma(const float* __restrict__ X, const float* __restrict__ CB,
             float* __restrict__ Y) {
    extern __shared__ char smem[];
    if (blockIdx.x < NBIG) {
        rvq_body<128>(X, CB, Y, smem, (long long)blockIdx.x * 128);
    } else {
        rvq_body<64>(X, CB, Y, smem,
                     (long long)NBIG * 128 + (long long)(blockIdx.x - NBIG) * 64);
    }
}

// ---------------------------------------------------------------------------
__global__ void finalize_kernel(float* __restrict__ Y, int out_size) {
    __shared__ double sd[1024];
    int tid = threadIdx.x;
    sd[tid] = (tid < GRID) ? g_commitPartial[tid] : 0.0;
    for (int s = 512; s > 0; s >>= 1) {
        __syncthreads();
        if (tid < s) sd[tid] += sd[tid + s];
    }
    if (tid == 0) {
        double mean = sd[0] / (double)((long long)NTOK * DDIM);
        float commit = (float)(0.25 * mean);
        long long numel = (long long)NTOK * DDIM;
        for (long long j = numel; j < (long long)out_size; j++) Y[j] = commit;
    }
}

extern "C" void kernel_launch(void* const* d_in, const int* in_sizes, int n_in,
                              void* d_out, int out_size) {
    const float* X  = (const float*)d_in[0];
    const float* CB = (const float*)d_in[1];
    float* Y = (float*)d_out;

    cudaFuncSetAttribute(rvq_mma, cudaFuncAttributeMaxDynamicSharedMemorySize,
                         SMEM_TOTAL);

    prep_all<<<512, 256>>>(CB);
    rvq_mma<<<GRID, THREADS, SMEM_TOTAL>>>(X, CB, Y);
    finalize_kernel<<<1, 1024>>>(Y, out_size);
}